// round 7
// baseline (speedup 1.0000x reference)
#include <cuda_runtime.h>
#include <cstdint>
#include <math.h>

#define B_   2
#define S_   2048
#define DM_  1024
#define NH_  16
#define NKV_ 4
#define DH_  64
#define M_   (B_*S_)   // 4096

// ---------------- scratch (device globals; no allocation allowed) ----------
__device__ float g_xr[(size_t)M_*1024];           // tf32-rounded x
__device__ float g_qkv[(size_t)M_*1536];          // fused [m][1536]
__device__ float g_Q[(size_t)B_*NH_*S_*DH_];
__device__ float g_K[(size_t)B_*NKV_*S_*DH_];
__device__ float g_V[(size_t)B_*NKV_*S_*DH_];
__device__ float g_ctx[(size_t)M_*1024];          // tf32-rounded by attention epilogue
__device__ float g_WqkvT[(size_t)1536*1024];      // [N][K] tf32-rounded, fused
__device__ float g_WoT[(size_t)1024*1024];

__device__ __forceinline__ float to_tf32(float x) {
    float y;
    asm("cvt.rna.tf32.f32 %0, %1;" : "=f"(y) : "f"(x));
    return y;
}

#define MMA_TF32(c0,c1,c2,c3,a0,a1,a2,a3,b0,b1) \
    asm volatile("mma.sync.aligned.m16n8k8.row.col.f32.tf32.tf32.f32 " \
        "{%0,%1,%2,%3}, {%4,%5,%6,%7}, {%8,%9}, {%0,%1,%2,%3};" \
        : "+f"(c0), "+f"(c1), "+f"(c2), "+f"(c3) \
        : "r"(a0), "r"(a1), "r"(a2), "r"(a3), "r"(b0), "r"(b1))

__device__ __forceinline__ void cp16(uint32_t smem_addr, const void* gptr) {
    asm volatile("cp.async.cg.shared.global [%0], [%1], 16;" :: "r"(smem_addr), "l"(gptr));
}
#define CP_COMMIT() asm volatile("cp.async.commit_group;" ::: "memory")
#define CP_WAIT1()  asm volatile("cp.async.wait_group 1;" ::: "memory")

// ---------------- pre-round x to tf32 ---------------------------------------
__global__ __launch_bounds__(256) void xround(const float* __restrict__ x,
                                              float* __restrict__ xr)
{
    const int i = (blockIdx.x * 256 + threadIdx.x) << 2;
    float4 v = *(const float4*)(x + i);
    v.x = to_tf32(v.x); v.y = to_tf32(v.y);
    v.z = to_tf32(v.z); v.w = to_tf32(v.w);
    *(float4*)(xr + i) = v;
}

// ---------------- fused weight transpose + tf32 round (4 matrices) ----------
// z: 0=Wq(N=1024,off 0) 1=Wk(N=256,off 1024*1024) 2=Wv(N=256,off 1280*1024) 3=Wo
__global__ __launch_bounds__(256) void wtrans4(const float* __restrict__ Wq,
                                               const float* __restrict__ Wk,
                                               const float* __restrict__ Wv,
                                               const float* __restrict__ Wo,
                                               float* __restrict__ WqkvT,
                                               float* __restrict__ WoT)
{
    const int z = blockIdx.z;
    const float* W;
    float* WT;
    int Ndim;
    if (z == 0)      { W = Wq; WT = WqkvT;                        Ndim = 1024; }
    else if (z == 1) { W = Wk; WT = WqkvT + (size_t)1024 * 1024;  Ndim = 256; }
    else if (z == 2) { W = Wv; WT = WqkvT + (size_t)1280 * 1024;  Ndim = 256; }
    else             { W = Wo; WT = WoT;                          Ndim = 1024; }
    const int n0 = blockIdx.x * 32;
    if (n0 >= Ndim) return;
    const int k0 = blockIdx.y * 32;

    __shared__ float t[32][33];
    const int tx = threadIdx.x, ty = threadIdx.y;   // 32 x 8
#pragma unroll
    for (int i = 0; i < 32; i += 8)
        t[ty + i][tx] = W[(size_t)(k0 + ty + i) * Ndim + n0 + tx];
    __syncthreads();
#pragma unroll
    for (int i = 0; i < 32; i += 8)
        WT[(size_t)(n0 + ty + i) * 1024 + k0 + tx] = to_tf32(t[tx][ty + i]);
}

// ---------------- tf32 mma.sync GEMM, cp.async double-buffered --------------
// C[M,N] = A[M,K] @ BT[N,K]^T. A and BT must already be tf32-rounded.
// 128x128 block tile, 256 threads = 8 warps (4m x 2n), warp 32x64, K-chunk 32.
#define KP 36
__global__ __launch_bounds__(256) void tgemm(const float* __restrict__ A,
                                             const float* __restrict__ BT,
                                             float* __restrict__ C,
                                             int Ndim, int Kdim)
{
    extern __shared__ float sm[];
    float (*As)[128][KP] = (float (*)[128][KP])sm;                 // [2][128][KP]
    float (*Bs)[128][KP] = (float (*)[128][KP])(sm + 2 * 128 * KP);

    const int tid = threadIdx.x;
    const int wid = tid >> 5, lane = tid & 31;
    const int g = lane >> 2, tg = lane & 3;
    const int wm = wid & 3, wn = wid >> 2;
    const int rowBase = blockIdx.y << 7;
    const int colBase = blockIdx.x << 7;

    const int cr = tid >> 3, cj = (tid & 7) << 2;   // copy row (x2), col
    const uint32_t sA0 = (uint32_t)__cvta_generic_to_shared(&As[0][cr][cj]);
    const uint32_t sA1 = (uint32_t)__cvta_generic_to_shared(&As[1][cr][cj]);
    const uint32_t sB0 = (uint32_t)__cvta_generic_to_shared(&Bs[0][cr][cj]);
    const uint32_t sB1 = (uint32_t)__cvta_generic_to_shared(&Bs[1][cr][cj]);
    const size_t rowStrideB = (size_t)32 * Kdim;    // 32 rows per copy step
    const float* Agp = A + (size_t)(rowBase + cr) * Kdim + cj;
    const float* Bgp = BT + (size_t)(colBase + cr) * Kdim + cj;

    float c[2][8][4];
#pragma unroll
    for (int mt = 0; mt < 2; mt++)
#pragma unroll
        for (int nt = 0; nt < 8; nt++)
#pragma unroll
            for (int r = 0; r < 4; r++) c[mt][nt][r] = 0.f;

    const int nchunk = Kdim >> 5;

    // prologue: stage chunk 0 into buf 0
#pragma unroll
    for (int i = 0; i < 4; i++) {
        cp16(sA0 + i * 32 * KP * 4, Agp + i * rowStrideB);
        cp16(sB0 + i * 32 * KP * 4, Bgp + i * rowStrideB);
    }
    CP_COMMIT();

    for (int ch = 0; ch < nchunk; ch++) {
        const int buf = ch & 1;
        // issue next chunk into other buffer
        if (ch + 1 < nchunk) {
            const uint32_t dA = buf ? sA0 : sA1;
            const uint32_t dB = buf ? sB0 : sB1;
            const float* An = Agp + ((ch + 1) << 5);
            const float* Bn = Bgp + ((ch + 1) << 5);
#pragma unroll
            for (int i = 0; i < 4; i++) {
                cp16(dA + i * 32 * KP * 4, An + i * rowStrideB);
                cp16(dB + i * 32 * KP * 4, Bn + i * rowStrideB);
            }
        }
        CP_COMMIT();
        CP_WAIT1();          // chunk ch resident
        __syncthreads();

        const uint32_t* As32 = (const uint32_t*)&As[buf][0][0];
        const uint32_t* Bs32 = (const uint32_t*)&Bs[buf][0][0];
#pragma unroll
        for (int ks = 0; ks < 4; ks++) {
            const int kk = ks << 3;
            uint32_t a[2][4], b[8][2];
#pragma unroll
            for (int mt = 0; mt < 2; mt++) {
                const int rA = ((wm << 5) + (mt << 4) + g) * KP + kk + tg;
                a[mt][0] = As32[rA];
                a[mt][1] = As32[rA + 8 * KP];
                a[mt][2] = As32[rA + 4];
                a[mt][3] = As32[rA + 8 * KP + 4];
            }
#pragma unroll
            for (int nt = 0; nt < 8; nt++) {
                const int rB = ((wn << 6) + (nt << 3) + g) * KP + kk + tg;
                b[nt][0] = Bs32[rB];
                b[nt][1] = Bs32[rB + 4];
            }
#pragma unroll
            for (int mt = 0; mt < 2; mt++)
#pragma unroll
                for (int nt = 0; nt < 8; nt++)
                    MMA_TF32(c[mt][nt][0], c[mt][nt][1], c[mt][nt][2], c[mt][nt][3],
                             a[mt][0], a[mt][1], a[mt][2], a[mt][3],
                             b[nt][0], b[nt][1]);
        }
        __syncthreads();     // done reading buf before it is overwritten
    }

#pragma unroll
    for (int mt = 0; mt < 2; mt++) {
        const int row0 = rowBase + (wm << 5) + (mt << 4) + g;
#pragma unroll
        for (int nt = 0; nt < 8; nt++) {
            const int col = colBase + (wn << 6) + (nt << 3) + (tg << 1);
            *(float2*)(C + (size_t)row0 * Ndim + col)       = make_float2(c[mt][nt][0], c[mt][nt][1]);
            *(float2*)(C + (size_t)(row0 + 8) * Ndim + col) = make_float2(c[mt][nt][2], c[mt][nt][3]);
        }
    }
}

// ---------------- L2-normalize + RoPE + transpose to [b,h,s,d] -------------
__global__ __launch_bounds__(256) void normrope_kernel(const float* __restrict__ cosb,
                                                       const float* __restrict__ sinb)
{
    const int gwarp = (blockIdx.x * blockDim.x + threadIdx.x) >> 5;
    const int lane = threadIdx.x & 31;
    if (gwarp >= M_ * 24) return;
    const int slot = gwarp % 24;
    const int m = gwarp / 24;
    const int b = m / S_, s = m % S_;

    if (slot < 16) {
        const int h = slot;
        const float* src = g_qkv + (size_t)m * 1536 + h * 64;
        float v0 = src[lane], v1 = src[lane + 32];
        float ss = v0 * v0 + v1 * v1;
#pragma unroll
        for (int o = 16; o; o >>= 1) ss += __shfl_xor_sync(0xffffffffu, ss, o);
        float inv = 1.0f / (sqrtf(ss) + 1e-8f);
        float x1 = v0 * inv, x2 = v1 * inv;
        float cc = cosb[s * 32 + lane], sn = sinb[s * 32 + lane];
        float* dst = g_Q + ((size_t)(b * NH_ + h) * S_ + s) * DH_;
        dst[lane]      = x1 * cc - x2 * sn;
        dst[lane + 32] = x1 * sn + x2 * cc;
    } else if (slot < 20) {
        const int h = slot - 16;
        const float* src = g_qkv + (size_t)m * 1536 + 1024 + h * 64;
        float v0 = src[lane], v1 = src[lane + 32];
        float ss = v0 * v0 + v1 * v1;
#pragma unroll
        for (int o = 16; o; o >>= 1) ss += __shfl_xor_sync(0xffffffffu, ss, o);
        float inv = 1.0f / (sqrtf(ss) + 1e-8f);
        float x1 = v0 * inv, x2 = v1 * inv;
        float cc = cosb[s * 32 + lane], sn = sinb[s * 32 + lane];
        float* dst = g_K + ((size_t)(b * NKV_ + h) * S_ + s) * DH_;
        dst[lane]      = x1 * cc - x2 * sn;
        dst[lane + 32] = x1 * sn + x2 * cc;
    } else {
        const int h = slot - 20;
        const float* src = g_qkv + (size_t)m * 1536 + 1280 + h * 64;
        float* dst = g_V + ((size_t)(b * NKV_ + h) * S_ + s) * DH_;
        dst[lane]      = src[lane];
        dst[lane + 32] = src[lane + 32];
    }
}

// ---------------- tensor-core attention -------------------------------------
#define AP 68
__global__ __launch_bounds__(128) void attn_kernel()
{
    extern __shared__ float sm[];
    float* Qs = sm;                 // [64 q][AP]  (tf32)
    float* Ks = sm + 64 * AP;       // [64 k][AP]  (tf32)
    float* Vt = sm + 2 * 64 * AP;   // [64 d][AP keys] (tf32, transposed)
    float* Ps = sm + 3 * 64 * AP;   // [64 q][AP keys]

    const int qt = blockIdx.x, h = blockIdx.y, b = blockIdx.z;
    const int qs = qt << 6;
    const int tid = threadIdx.x;
    const int wid = tid >> 5, lane = tid & 31;
    const int g = lane >> 2, tg = lane & 3;
    const int hk = h >> 2;

    const float* Qg = g_Q + (size_t)(b * NH_ + h) * S_ * DH_;
    const float* Kg = g_K + (size_t)(b * NKV_ + hk) * S_ * DH_;
    const float* Vg = g_V + (size_t)(b * NKV_ + hk) * S_ * DH_;

    {
        const int r = tid >> 1, c0 = (tid & 1) << 5;
        const float* src = Qg + (size_t)(qs + r) * DH_ + c0;
#pragma unroll
        for (int i = 0; i < 8; i++) {
            float4 v = *(const float4*)(src + i * 4);
            v.x = to_tf32(v.x); v.y = to_tf32(v.y);
            v.z = to_tf32(v.z); v.w = to_tf32(v.w);
            *(float4*)&Qs[r * AP + c0 + i * 4] = v;
        }
    }

    float o[8][4];
#pragma unroll
    for (int nt = 0; nt < 8; nt++)
#pragma unroll
        for (int r = 0; r < 4; r++) o[nt][r] = 0.f;
    float l0 = 0.f, l1 = 0.f;

    const int row0 = qs + wid * 16 + g;
    const int qrow = wid * 16 + g;

    const int t_lo = (qs > 255) ? ((qs - 255) >> 6) : 0;
    const int extra = (t_lo > 0) ? 1 : 0;
    const int ntiles = (qt - t_lo + 1) + extra;

    for (int it = 0; it < ntiles; it++) {
        const int kt = (extra && it == 0) ? 0 : (t_lo + it - extra);
        const int ks = kt << 6;
        __syncthreads();
        {
            const int r = tid >> 1, c0 = (tid & 1) << 5;
            const float* ksrc = Kg + (size_t)(ks + r) * DH_ + c0;
            const float* vsrc = Vg + (size_t)(ks + r) * DH_ + c0;
#pragma unroll
            for (int i = 0; i < 8; i++) {
                float4 v = *(const float4*)(ksrc + i * 4);
                v.x = to_tf32(v.x); v.y = to_tf32(v.y);
                v.z = to_tf32(v.z); v.w = to_tf32(v.w);
                *(float4*)&Ks[r * AP + c0 + i * 4] = v;
                float4 w = *(const float4*)(vsrc + i * 4);
                const int d = c0 + i * 4;
                Vt[(d + 0) * AP + r] = to_tf32(w.x);
                Vt[(d + 1) * AP + r] = to_tf32(w.y);
                Vt[(d + 2) * AP + r] = to_tf32(w.z);
                Vt[(d + 3) * AP + r] = to_tf32(w.w);
            }
        }
        __syncthreads();

        float c[8][4];
#pragma unroll
        for (int nt = 0; nt < 8; nt++)
#pragma unroll
            for (int r = 0; r < 4; r++) c[nt][r] = 0.f;

        const uint32_t* Q32 = (const uint32_t*)Qs;
        const uint32_t* K32 = (const uint32_t*)Ks;
#pragma unroll
        for (int kk = 0; kk < 8; kk++) {
            const int kb = kk << 3;
            uint32_t a0 = Q32[qrow * AP + kb + tg];
            uint32_t a1 = Q32[(qrow + 8) * AP + kb + tg];
            uint32_t a2 = Q32[qrow * AP + kb + tg + 4];
            uint32_t a3 = Q32[(qrow + 8) * AP + kb + tg + 4];
#pragma unroll
            for (int nt = 0; nt < 8; nt++) {
                uint32_t b0 = K32[(nt * 8 + g) * AP + kb + tg];
                uint32_t b1 = K32[(nt * 8 + g) * AP + kb + tg + 4];
                MMA_TF32(c[nt][0], c[nt][1], c[nt][2], c[nt][3], a0, a1, a2, a3, b0, b1);
            }
        }

#pragma unroll
        for (int nt = 0; nt < 8; nt++) {
            float p[4];
#pragma unroll
            for (int i = 0; i < 4; i++) {
                const int key = ks + nt * 8 + (tg << 1) + (i & 1);
                const int row = row0 + ((i >> 1) << 3);
                const bool valid = (key <= row) && ((key > row - 256) || (key < 4));
                float t = c[nt][i] * 0.125f;
                float u = t - t * t * t * 1.4814815e-3f;
                float e = fmaf(u, 0.041666668f, 0.16666667f);
                e = fmaf(u, e, 0.5f);
                e = fmaf(u, e, 1.0f);
                e = fmaf(u, e, 1.0f);
                p[i] = valid ? to_tf32(e) : 0.f;
            }
            l0 += p[0] + p[1];
            l1 += p[2] + p[3];
            *(float2*)&Ps[qrow * AP + nt * 8 + (tg << 1)]       = make_float2(p[0], p[1]);
            *(float2*)&Ps[(qrow + 8) * AP + nt * 8 + (tg << 1)] = make_float2(p[2], p[3]);
        }
        __syncwarp();

        const uint32_t* P32 = (const uint32_t*)Ps;
        const uint32_t* V32 = (const uint32_t*)Vt;
#pragma unroll
        for (int kk = 0; kk < 8; kk++) {
            const int kb = kk << 3;
            uint32_t a0 = P32[qrow * AP + kb + tg];
            uint32_t a1 = P32[(qrow + 8) * AP + kb + tg];
            uint32_t a2 = P32[qrow * AP + kb + tg + 4];
            uint32_t a3 = P32[(qrow + 8) * AP + kb + tg + 4];
#pragma unroll
            for (int nt = 0; nt < 8; nt++) {
                uint32_t b0 = V32[(nt * 8 + g) * AP + kb + tg];
                uint32_t b1 = V32[(nt * 8 + g) * AP + kb + tg + 4];
                MMA_TF32(o[nt][0], o[nt][1], o[nt][2], o[nt][3], a0, a1, a2, a3, b0, b1);
            }
        }
    }

    l0 += __shfl_xor_sync(0xffffffffu, l0, 1);
    l0 += __shfl_xor_sync(0xffffffffu, l0, 2);
    l1 += __shfl_xor_sync(0xffffffffu, l1, 1);
    l1 += __shfl_xor_sync(0xffffffffu, l1, 2);
    const float inv0 = 1.0f / l0, inv1 = 1.0f / l1;

    // ctx written tf32-rounded so the output-projection GEMM can cp.async it raw
    float* ctx0 = g_ctx + (size_t)(b * S_ + row0) * 1024 + h * 64;
    float* ctx1 = ctx0 + (size_t)8 * 1024;
#pragma unroll
    for (int nt = 0; nt < 8; nt++) {
        const int d = nt * 8 + (tg << 1);
        *(float2*)(ctx0 + d) = make_float2(to_tf32(o[nt][0] * inv0), to_tf32(o[nt][1] * inv0));
        *(float2*)(ctx1 + d) = make_float2(to_tf32(o[nt][2] * inv1), to_tf32(o[nt][3] * inv1));
    }
}

// ---------------- launch -----------------------------------------------------
extern "C" void kernel_launch(void* const* d_in, const int* in_sizes, int n_in,
                              void* d_out, int out_size)
{
    const float* x    = (const float*)d_in[0];
    const float* cosb = (const float*)d_in[1];
    const float* sinb = (const float*)d_in[2];
    const float* Wq   = (const float*)d_in[4];
    const float* Wk   = (const float*)d_in[5];
    const float* Wv   = (const float*)d_in[6];
    const float* Wo   = (const float*)d_in[7];
    float* out = (float*)d_out;

    float *xr, *qkv, *ctx, *wqkvT, *woT;
    cudaGetSymbolAddress((void**)&xr,    g_xr);
    cudaGetSymbolAddress((void**)&qkv,   g_qkv);
    cudaGetSymbolAddress((void**)&ctx,   g_ctx);
    cudaGetSymbolAddress((void**)&wqkvT, g_WqkvT);
    cudaGetSymbolAddress((void**)&woT,   g_WoT);

    xround<<<(M_ * 1024) / (256 * 4), 256>>>(x, xr);
    wtrans4<<<dim3(32, 32, 4), dim3(32, 8)>>>(Wq, Wk, Wv, Wo, wqkvT, woT);

    const int gsmem = 4 * 128 * KP * (int)sizeof(float);   // 2 bufs x (A+B)
    cudaFuncSetAttribute(tgemm, cudaFuncAttributeMaxDynamicSharedMemorySize, gsmem);

    tgemm<<<dim3(12, 32), 256, gsmem>>>(xr, wqkvT, qkv, 1536, 1024);

    normrope_kernel<<<(M_ * 24) / 8, 256>>>(cosb, sinb);

    const int asmem = 4 * 64 * AP * (int)sizeof(float);
    cudaFuncSetAttribute(attn_kernel, cudaFuncAttributeMaxDynamicSharedMemorySize, asmem);
    attn_kernel<<<dim3(S_ / 64, NH_, B_), 128, asmem>>>();

    tgemm<<<dim3(8, 32), 256, gsmem>>>(ctx, woT, out, 1024, 1024);
}

// round 8
// speedup vs baseline: 1.1409x; 1.1409x over previous
#include <cuda_runtime.h>
#include <cstdint>
#include <math.h>

#define B_   2
#define S_   2048
#define DM_  1024
#define NH_  16
#define NKV_ 4
#define DH_  64
#define M_   (B_*S_)   // 4096

// ---------------- scratch (device globals; no allocation allowed) ----------
__device__ float g_xr[(size_t)M_*1024];           // tf32-rounded x
__device__ float g_qkv[(size_t)M_*1536];          // fused [m][1536]
__device__ float g_Q[(size_t)B_*NH_*S_*DH_];      // tf32-rounded
__device__ float g_K[(size_t)B_*NKV_*S_*DH_];     // tf32-rounded
__device__ float g_V[(size_t)B_*NKV_*S_*DH_];     // tf32-rounded
__device__ float g_ctx[(size_t)M_*1024];          // tf32-rounded
__device__ float g_WqkvT[(size_t)1536*1024];      // [N][K] tf32-rounded, fused
__device__ float g_WoT[(size_t)1024*1024];

__device__ __forceinline__ float to_tf32(float x) {
    float y;
    asm("cvt.rna.tf32.f32 %0, %1;" : "=f"(y) : "f"(x));
    return y;
}

#define MMA_TF32(c0,c1,c2,c3,a0,a1,a2,a3,b0,b1) \
    asm volatile("mma.sync.aligned.m16n8k8.row.col.f32.tf32.tf32.f32 " \
        "{%0,%1,%2,%3}, {%4,%5,%6,%7}, {%8,%9}, {%0,%1,%2,%3};" \
        : "+f"(c0), "+f"(c1), "+f"(c2), "+f"(c3) \
        : "r"(a0), "r"(a1), "r"(a2), "r"(a3), "r"(b0), "r"(b1))

__device__ __forceinline__ void cp16(uint32_t smem_addr, const void* gptr) {
    asm volatile("cp.async.cg.shared.global [%0], [%1], 16;" :: "r"(smem_addr), "l"(gptr));
}
#define CP_COMMIT() asm volatile("cp.async.commit_group;" ::: "memory")
#define CP_WAIT1()  asm volatile("cp.async.wait_group 1;" ::: "memory")

// ---------------- pre-round x to tf32 ---------------------------------------
__global__ __launch_bounds__(256) void xround(const float* __restrict__ x,
                                              float* __restrict__ xr)
{
    const int i = (blockIdx.x * 256 + threadIdx.x) << 2;
    float4 v = *(const float4*)(x + i);
    v.x = to_tf32(v.x); v.y = to_tf32(v.y);
    v.z = to_tf32(v.z); v.w = to_tf32(v.w);
    *(float4*)(xr + i) = v;
}

// ---------------- fused weight transpose + tf32 round (4 matrices) ----------
__global__ __launch_bounds__(256) void wtrans4(const float* __restrict__ Wq,
                                               const float* __restrict__ Wk,
                                               const float* __restrict__ Wv,
                                               const float* __restrict__ Wo,
                                               float* __restrict__ WqkvT,
                                               float* __restrict__ WoT)
{
    const int z = blockIdx.z;
    const float* W;
    float* WT;
    int Ndim;
    if (z == 0)      { W = Wq; WT = WqkvT;                        Ndim = 1024; }
    else if (z == 1) { W = Wk; WT = WqkvT + (size_t)1024 * 1024;  Ndim = 256; }
    else if (z == 2) { W = Wv; WT = WqkvT + (size_t)1280 * 1024;  Ndim = 256; }
    else             { W = Wo; WT = WoT;                          Ndim = 1024; }
    const int n0 = blockIdx.x * 32;
    if (n0 >= Ndim) return;
    const int k0 = blockIdx.y * 32;

    __shared__ float t[32][33];
    const int tx = threadIdx.x, ty = threadIdx.y;
#pragma unroll
    for (int i = 0; i < 32; i += 8)
        t[ty + i][tx] = W[(size_t)(k0 + ty + i) * Ndim + n0 + tx];
    __syncthreads();
#pragma unroll
    for (int i = 0; i < 32; i += 8)
        WT[(size_t)(n0 + ty + i) * 1024 + k0 + tx] = to_tf32(t[tx][ty + i]);
}

// ---------------- tf32 mma.sync GEMM, cp.async double-buffered --------------
#define KP 36
__global__ __launch_bounds__(256) void tgemm(const float* __restrict__ A,
                                             const float* __restrict__ BT,
                                             float* __restrict__ C,
                                             int Ndim, int Kdim)
{
    extern __shared__ float sm[];
    float (*As)[128][KP] = (float (*)[128][KP])sm;
    float (*Bs)[128][KP] = (float (*)[128][KP])(sm + 2 * 128 * KP);

    const int tid = threadIdx.x;
    const int wid = tid >> 5, lane = tid & 31;
    const int g = lane >> 2, tg = lane & 3;
    const int wm = wid & 3, wn = wid >> 2;
    const int rowBase = blockIdx.y << 7;
    const int colBase = blockIdx.x << 7;

    const int cr = tid >> 3, cj = (tid & 7) << 2;
    const uint32_t sA0 = (uint32_t)__cvta_generic_to_shared(&As[0][cr][cj]);
    const uint32_t sA1 = (uint32_t)__cvta_generic_to_shared(&As[1][cr][cj]);
    const uint32_t sB0 = (uint32_t)__cvta_generic_to_shared(&Bs[0][cr][cj]);
    const uint32_t sB1 = (uint32_t)__cvta_generic_to_shared(&Bs[1][cr][cj]);
    const size_t rowStrideB = (size_t)32 * Kdim;
    const float* Agp = A + (size_t)(rowBase + cr) * Kdim + cj;
    const float* Bgp = BT + (size_t)(colBase + cr) * Kdim + cj;

    float c[2][8][4];
#pragma unroll
    for (int mt = 0; mt < 2; mt++)
#pragma unroll
        for (int nt = 0; nt < 8; nt++)
#pragma unroll
            for (int r = 0; r < 4; r++) c[mt][nt][r] = 0.f;

    const int nchunk = Kdim >> 5;
#pragma unroll
    for (int i = 0; i < 4; i++) {
        cp16(sA0 + i * 32 * KP * 4, Agp + i * rowStrideB);
        cp16(sB0 + i * 32 * KP * 4, Bgp + i * rowStrideB);
    }
    CP_COMMIT();

    for (int ch = 0; ch < nchunk; ch++) {
        const int buf = ch & 1;
        if (ch + 1 < nchunk) {
            const uint32_t dA = buf ? sA0 : sA1;
            const uint32_t dB = buf ? sB0 : sB1;
            const float* An = Agp + ((ch + 1) << 5);
            const float* Bn = Bgp + ((ch + 1) << 5);
#pragma unroll
            for (int i = 0; i < 4; i++) {
                cp16(dA + i * 32 * KP * 4, An + i * rowStrideB);
                cp16(dB + i * 32 * KP * 4, Bn + i * rowStrideB);
            }
        }
        CP_COMMIT();
        CP_WAIT1();
        __syncthreads();

        const uint32_t* As32 = (const uint32_t*)&As[buf][0][0];
        const uint32_t* Bs32 = (const uint32_t*)&Bs[buf][0][0];
#pragma unroll
        for (int ks = 0; ks < 4; ks++) {
            const int kk = ks << 3;
            uint32_t a[2][4], b[8][2];
#pragma unroll
            for (int mt = 0; mt < 2; mt++) {
                const int rA = ((wm << 5) + (mt << 4) + g) * KP + kk + tg;
                a[mt][0] = As32[rA];
                a[mt][1] = As32[rA + 8 * KP];
                a[mt][2] = As32[rA + 4];
                a[mt][3] = As32[rA + 8 * KP + 4];
            }
#pragma unroll
            for (int nt = 0; nt < 8; nt++) {
                const int rB = ((wn << 6) + (nt << 3) + g) * KP + kk + tg;
                b[nt][0] = Bs32[rB];
                b[nt][1] = Bs32[rB + 4];
            }
#pragma unroll
            for (int mt = 0; mt < 2; mt++)
#pragma unroll
                for (int nt = 0; nt < 8; nt++)
                    MMA_TF32(c[mt][nt][0], c[mt][nt][1], c[mt][nt][2], c[mt][nt][3],
                             a[mt][0], a[mt][1], a[mt][2], a[mt][3],
                             b[nt][0], b[nt][1]);
        }
        __syncthreads();
    }

#pragma unroll
    for (int mt = 0; mt < 2; mt++) {
        const int row0 = rowBase + (wm << 5) + (mt << 4) + g;
#pragma unroll
        for (int nt = 0; nt < 8; nt++) {
            const int col = colBase + (wn << 6) + (nt << 3) + (tg << 1);
            *(float2*)(C + (size_t)row0 * Ndim + col)       = make_float2(c[mt][nt][0], c[mt][nt][1]);
            *(float2*)(C + (size_t)(row0 + 8) * Ndim + col) = make_float2(c[mt][nt][2], c[mt][nt][3]);
        }
    }
}

// ---------------- L2-normalize + RoPE; outputs tf32-rounded -----------------
__global__ __launch_bounds__(256) void normrope_kernel(const float* __restrict__ cosb,
                                                       const float* __restrict__ sinb)
{
    const int gwarp = (blockIdx.x * blockDim.x + threadIdx.x) >> 5;
    const int lane = threadIdx.x & 31;
    if (gwarp >= M_ * 24) return;
    const int slot = gwarp % 24;
    const int m = gwarp / 24;
    const int b = m / S_, s = m % S_;

    if (slot < 16) {
        const int h = slot;
        const float* src = g_qkv + (size_t)m * 1536 + h * 64;
        float v0 = src[lane], v1 = src[lane + 32];
        float ss = v0 * v0 + v1 * v1;
#pragma unroll
        for (int o = 16; o; o >>= 1) ss += __shfl_xor_sync(0xffffffffu, ss, o);
        float inv = 1.0f / (sqrtf(ss) + 1e-8f);
        float x1 = v0 * inv, x2 = v1 * inv;
        float cc = cosb[s * 32 + lane], sn = sinb[s * 32 + lane];
        float* dst = g_Q + ((size_t)(b * NH_ + h) * S_ + s) * DH_;
        dst[lane]      = to_tf32(x1 * cc - x2 * sn);
        dst[lane + 32] = to_tf32(x1 * sn + x2 * cc);
    } else if (slot < 20) {
        const int h = slot - 16;
        const float* src = g_qkv + (size_t)m * 1536 + 1024 + h * 64;
        float v0 = src[lane], v1 = src[lane + 32];
        float ss = v0 * v0 + v1 * v1;
#pragma unroll
        for (int o = 16; o; o >>= 1) ss += __shfl_xor_sync(0xffffffffu, ss, o);
        float inv = 1.0f / (sqrtf(ss) + 1e-8f);
        float x1 = v0 * inv, x2 = v1 * inv;
        float cc = cosb[s * 32 + lane], sn = sinb[s * 32 + lane];
        float* dst = g_K + ((size_t)(b * NKV_ + h) * S_ + s) * DH_;
        dst[lane]      = to_tf32(x1 * cc - x2 * sn);
        dst[lane + 32] = to_tf32(x1 * sn + x2 * cc);
    } else {
        const int h = slot - 20;
        const float* src = g_qkv + (size_t)m * 1536 + 1280 + h * 64;
        float* dst = g_V + ((size_t)(b * NKV_ + h) * S_ + s) * DH_;
        dst[lane]      = to_tf32(src[lane]);
        dst[lane + 32] = to_tf32(src[lane + 32]);
    }
}

// ---------------- GQA tensor-core attention ---------------------------------
// CTA = 64 queries x 4 heads (one KV group). 256 threads, 8 warps.
// Warp w: head hq = w>>1, query rows (w&1)*32 + [0,32). Q fragments in regs.
// K/V staged once per tile for all 4 heads, cp.async double-buffered.
// K,P stride 68; V stride 72 (natural [key][d], conflict-free B frags).
#define KS_ 68
#define VS_ 72
__global__ __launch_bounds__(256) void attn_kernel()
{
    extern __shared__ float sm[];
    float* Ksm = sm;                    // [2][64*KS_]
    float* Vsm = sm + 2 * 64 * KS_;     // [2][64*VS_]
    float* Ps  = sm + 2 * 64 * (KS_ + VS_);   // [256][KS_]

    const int qt = blockIdx.x, hk = blockIdx.y, b = blockIdx.z;
    const int qs = qt << 6;
    const int tid = threadIdx.x;
    const int wid = tid >> 5, lane = tid & 31;
    const int g = lane >> 2, tg = lane & 3;
    const int hq = wid >> 1, half = wid & 1;
    const int h = (hk << 2) + hq;

    const float* Qg = g_Q + (size_t)(b * NH_ + h) * S_ * DH_;
    const float* Kg = g_K + (size_t)(b * NKV_ + hk) * S_ * DH_;
    const float* Vg = g_V + (size_t)(b * NKV_ + hk) * S_ * DH_;

    // Q fragments -> registers (reused across all key tiles)
    uint32_t qa[2][8][4];
    const int rloc = (half << 5) + g;           // local row (mt=0, lower 8x8)
#pragma unroll
    for (int mt = 0; mt < 2; mt++)
#pragma unroll
        for (int kk = 0; kk < 8; kk++) {
            const float* qp = Qg + (size_t)(qs + rloc + (mt << 4)) * DH_ + (kk << 3) + tg;
            qa[mt][kk][0] = __float_as_uint(qp[0]);
            qa[mt][kk][1] = __float_as_uint(qp[8 * DH_]);
            qa[mt][kk][2] = __float_as_uint(qp[4]);
            qa[mt][kk][3] = __float_as_uint(qp[8 * DH_ + 4]);
        }

    float o[2][8][4];
#pragma unroll
    for (int mt = 0; mt < 2; mt++)
#pragma unroll
        for (int nt = 0; nt < 8; nt++)
#pragma unroll
            for (int r = 0; r < 4; r++) o[mt][nt][r] = 0.f;
    float lacc[2][2] = {{0.f, 0.f}, {0.f, 0.f}};

    const int t_lo = (qs > 255) ? ((qs - 255) >> 6) : 0;
    const int extra = (t_lo > 0) ? 1 : 0;
    const int ntiles = (qt - t_lo + 1) + extra;

    // staging mapping: 4 threads/row, 16 floats per thread (4 cp16)
    const int sr = tid >> 2, sc = (tid & 3) << 4;
    const uint32_t kb0 = (uint32_t)__cvta_generic_to_shared(Ksm) + (sr * KS_ + sc) * 4;
    const uint32_t vb0 = (uint32_t)__cvta_generic_to_shared(Vsm) + (sr * VS_ + sc) * 4;
    const uint32_t kbufStride = 64 * KS_ * 4, vbufStride = 64 * VS_ * 4;

    // prologue: stage tile 0 into buf 0
    {
        const int ks0 = (extra ? 0 : t_lo) << 6;
        const float* kp = Kg + (size_t)(ks0 + sr) * DH_ + sc;
        const float* vp = Vg + (size_t)(ks0 + sr) * DH_ + sc;
#pragma unroll
        for (int j = 0; j < 4; j++) {
            cp16(kb0 + j * 16, kp + j * 4);
            cp16(vb0 + j * 16, vp + j * 4);
        }
    }
    CP_COMMIT();

    const int prow0 = (wid << 5) + g;           // this thread's P slab row (mt=0)

    for (int it = 0; it < ntiles; it++) {
        const int buf = it & 1;
        const int kt = (extra && it == 0) ? 0 : (t_lo + it - extra);
        const int ks = kt << 6;

        if (it + 1 < ntiles) {
            const int ktn = (extra && it + 1 == 1 && extra) ? (t_lo + 1 - extra) : (t_lo + it + 1 - extra);
            const int ksn = ((extra && it == 0) ? t_lo : (kt + 1)) << 6;
            (void)ktn;
            const uint32_t dk = kb0 + (buf ^ 1) * kbufStride;
            const uint32_t dv = vb0 + (buf ^ 1) * vbufStride;
            const float* kp = Kg + (size_t)(ksn + sr) * DH_ + sc;
            const float* vp = Vg + (size_t)(ksn + sr) * DH_ + sc;
#pragma unroll
            for (int j = 0; j < 4; j++) {
                cp16(dk + j * 16, kp + j * 4);
                cp16(dv + j * 16, vp + j * 4);
            }
        }
        CP_COMMIT();
        CP_WAIT1();
        __syncthreads();

        // S = Q K^T
        float c[2][8][4];
#pragma unroll
        for (int mt = 0; mt < 2; mt++)
#pragma unroll
            for (int nt = 0; nt < 8; nt++)
#pragma unroll
                for (int r = 0; r < 4; r++) c[mt][nt][r] = 0.f;

        const uint32_t* K32 = (const uint32_t*)(Ksm + buf * 64 * KS_);
#pragma unroll
        for (int kk = 0; kk < 8; kk++) {
            const int kb = kk << 3;
            uint32_t b0[8], b1[8];
#pragma unroll
            for (int nt = 0; nt < 8; nt++) {
                const int rB = ((nt << 3) + g) * KS_ + kb + tg;
                b0[nt] = K32[rB];
                b1[nt] = K32[rB + 4];
            }
#pragma unroll
            for (int mt = 0; mt < 2; mt++)
#pragma unroll
                for (int nt = 0; nt < 8; nt++)
                    MMA_TF32(c[mt][nt][0], c[mt][nt][1], c[mt][nt][2], c[mt][nt][3],
                             qa[mt][kk][0], qa[mt][kk][1], qa[mt][kk][2], qa[mt][kk][3],
                             b0[nt], b1[nt]);
        }

        // softcap + exp (poly) + mask -> P, l
#pragma unroll
        for (int mt = 0; mt < 2; mt++) {
            const int rowL = qs + rloc + (mt << 4);
#pragma unroll
            for (int nt = 0; nt < 8; nt++) {
                float p[4];
#pragma unroll
                for (int i = 0; i < 4; i++) {
                    const int key = ks + (nt << 3) + (tg << 1) + (i & 1);
                    const int row = rowL + ((i >> 1) << 3);
                    const bool valid = (key <= row) && ((key > row - 256) || (key < 4));
                    float t = c[mt][nt][i] * 0.125f;
                    float u = t - t * t * t * 1.4814815e-3f;
                    float e = fmaf(u, 0.041666668f, 0.16666667f);
                    e = fmaf(u, e, 0.5f);
                    e = fmaf(u, e, 1.0f);
                    e = fmaf(u, e, 1.0f);
                    p[i] = valid ? to_tf32(e) : 0.f;
                }
                lacc[mt][0] += p[0] + p[1];
                lacc[mt][1] += p[2] + p[3];
                const int pr = prow0 + (mt << 4);
                *(float2*)&Ps[pr * KS_ + (nt << 3) + (tg << 1)]       = make_float2(p[0], p[1]);
                *(float2*)&Ps[(pr + 8) * KS_ + (nt << 3) + (tg << 1)] = make_float2(p[2], p[3]);
            }
        }
        __syncwarp();

        // O += P V   (V natural layout: B frag b0 = V[kb+tg][nt*8+g])
        const uint32_t* P32 = (const uint32_t*)Ps;
        const uint32_t* V32 = (const uint32_t*)(Vsm + buf * 64 * VS_);
#pragma unroll
        for (int kk = 0; kk < 8; kk++) {
            const int kb = kk << 3;
            uint32_t a[2][4], b0[8], b1[8];
#pragma unroll
            for (int mt = 0; mt < 2; mt++) {
                const int rP = (prow0 + (mt << 4)) * KS_ + kb + tg;
                a[mt][0] = P32[rP];
                a[mt][1] = P32[rP + 8 * KS_];
                a[mt][2] = P32[rP + 4];
                a[mt][3] = P32[rP + 8 * KS_ + 4];
            }
#pragma unroll
            for (int nt = 0; nt < 8; nt++) {
                b0[nt] = V32[(kb + tg) * VS_ + (nt << 3) + g];
                b1[nt] = V32[(kb + tg + 4) * VS_ + (nt << 3) + g];
            }
#pragma unroll
            for (int mt = 0; mt < 2; mt++)
#pragma unroll
                for (int nt = 0; nt < 8; nt++)
                    MMA_TF32(o[mt][nt][0], o[mt][nt][1], o[mt][nt][2], o[mt][nt][3],
                             a[mt][0], a[mt][1], a[mt][2], a[mt][3],
                             b0[nt], b1[nt]);
        }
        __syncthreads();   // all warps done with buf before it is re-staged
    }

    // reduce l over quad, normalize, write ctx (tf32-rounded)
#pragma unroll
    for (int mt = 0; mt < 2; mt++)
#pragma unroll
        for (int u = 0; u < 2; u++) {
            lacc[mt][u] += __shfl_xor_sync(0xffffffffu, lacc[mt][u], 1);
            lacc[mt][u] += __shfl_xor_sync(0xffffffffu, lacc[mt][u], 2);
        }

#pragma unroll
    for (int mt = 0; mt < 2; mt++) {
        const int rowL = qs + rloc + (mt << 4);
        const float inv0 = 1.0f / lacc[mt][0];
        const float inv1 = 1.0f / lacc[mt][1];
        float* c0 = g_ctx + (size_t)(b * S_ + rowL) * 1024 + h * 64;
        float* c1 = c0 + (size_t)8 * 1024;
#pragma unroll
        for (int nt = 0; nt < 8; nt++) {
            const int d = (nt << 3) + (tg << 1);
            *(float2*)(c0 + d) = make_float2(to_tf32(o[mt][nt][0] * inv0),
                                             to_tf32(o[mt][nt][1] * inv0));
            *(float2*)(c1 + d) = make_float2(to_tf32(o[mt][nt][2] * inv1),
                                             to_tf32(o[mt][nt][3] * inv1));
        }
    }
}

// ---------------- launch -----------------------------------------------------
extern "C" void kernel_launch(void* const* d_in, const int* in_sizes, int n_in,
                              void* d_out, int out_size)
{
    const float* x    = (const float*)d_in[0];
    const float* cosb = (const float*)d_in[1];
    const float* sinb = (const float*)d_in[2];
    const float* Wq   = (const float*)d_in[4];
    const float* Wk   = (const float*)d_in[5];
    const float* Wv   = (const float*)d_in[6];
    const float* Wo   = (const float*)d_in[7];
    float* out = (float*)d_out;

    float *xr, *qkv, *ctx, *wqkvT, *woT;
    cudaGetSymbolAddress((void**)&xr,    g_xr);
    cudaGetSymbolAddress((void**)&qkv,   g_qkv);
    cudaGetSymbolAddress((void**)&ctx,   g_ctx);
    cudaGetSymbolAddress((void**)&wqkvT, g_WqkvT);
    cudaGetSymbolAddress((void**)&woT,   g_WoT);

    xround<<<(M_ * 1024) / (256 * 4), 256>>>(x, xr);
    wtrans4<<<dim3(32, 32, 4), dim3(32, 8)>>>(Wq, Wk, Wv, Wo, wqkvT, woT);

    const int gsmem = 4 * 128 * KP * (int)sizeof(float);
    cudaFuncSetAttribute(tgemm, cudaFuncAttributeMaxDynamicSharedMemorySize, gsmem);

    tgemm<<<dim3(12, 32), 256, gsmem>>>(xr, wqkvT, qkv, 1536, 1024);

    normrope_kernel<<<(M_ * 24) / 8, 256>>>(cosb, sinb);

    const int asmem = (2 * 64 * (KS_ + VS_) + 256 * KS_) * (int)sizeof(float);
    cudaFuncSetAttribute(attn_kernel, cudaFuncAttributeMaxDynamicSharedMemorySize, asmem);
    attn_kernel<<<dim3(S_ / 64, NKV_, B_), 256, asmem>>>();

    tgemm<<<dim3(8, 32), 256, gsmem>>>(ctx, woT, out, 1024, 1024);
}

// round 10
// speedup vs baseline: 1.1587x; 1.0156x over previous
#include <cuda_runtime.h>
#include <cstdint>
#include <math.h>

#define B_   2
#define S_   2048
#define DM_  1024
#define NH_  16
#define NKV_ 4
#define DH_  64
#define M_   (B_*S_)   // 4096

// ---------------- scratch (device globals; no allocation allowed) ----------
__device__ float g_xr[(size_t)M_*1024];           // tf32-rounded x
__device__ float g_qkv[(size_t)M_*1536];          // fused [m][1536]
__device__ float g_Q[(size_t)B_*NH_*S_*DH_];      // tf32-rounded
__device__ float g_K[(size_t)B_*NKV_*S_*DH_];     // tf32-rounded
__device__ float g_V[(size_t)B_*NKV_*S_*DH_];     // tf32-rounded
__device__ float g_ctx[(size_t)M_*1024];          // tf32-rounded
__device__ float g_WqkvT[(size_t)1536*1024];      // [N][K] tf32-rounded, fused
__device__ float g_WoT[(size_t)1024*1024];

__device__ __forceinline__ float to_tf32(float x) {
    float y;
    asm("cvt.rna.tf32.f32 %0, %1;" : "=f"(y) : "f"(x));
    return y;
}

#define MMA_TF32(c0,c1,c2,c3,a0,a1,a2,a3,b0,b1) \
    asm volatile("mma.sync.aligned.m16n8k8.row.col.f32.tf32.tf32.f32 " \
        "{%0,%1,%2,%3}, {%4,%5,%6,%7}, {%8,%9}, {%0,%1,%2,%3};" \
        : "+f"(c0), "+f"(c1), "+f"(c2), "+f"(c3) \
        : "r"(a0), "r"(a1), "r"(a2), "r"(a3), "r"(b0), "r"(b1))

__device__ __forceinline__ void cp16(uint32_t smem_addr, const void* gptr) {
    asm volatile("cp.async.cg.shared.global [%0], [%1], 16;" :: "r"(smem_addr), "l"(gptr));
}
#define CP_COMMIT() asm volatile("cp.async.commit_group;" ::: "memory")
#define CP_WAIT1()  asm volatile("cp.async.wait_group 1;" ::: "memory")

// ---------------- pre-round x to tf32 ---------------------------------------
__global__ __launch_bounds__(256) void xround(const float* __restrict__ x,
                                              float* __restrict__ xr)
{
    const int i = (blockIdx.x * 256 + threadIdx.x) << 2;
    float4 v = *(const float4*)(x + i);
    v.x = to_tf32(v.x); v.y = to_tf32(v.y);
    v.z = to_tf32(v.z); v.w = to_tf32(v.w);
    *(float4*)(xr + i) = v;
}

// ---------------- fused weight transpose + tf32 round (4 matrices) ----------
__global__ __launch_bounds__(256) void wtrans4(const float* __restrict__ Wq,
                                               const float* __restrict__ Wk,
                                               const float* __restrict__ Wv,
                                               const float* __restrict__ Wo,
                                               float* __restrict__ WqkvT,
                                               float* __restrict__ WoT)
{
    const int z = blockIdx.z;
    const float* W;
    float* WT;
    int Ndim;
    if (z == 0)      { W = Wq; WT = WqkvT;                        Ndim = 1024; }
    else if (z == 1) { W = Wk; WT = WqkvT + (size_t)1024 * 1024;  Ndim = 256; }
    else if (z == 2) { W = Wv; WT = WqkvT + (size_t)1280 * 1024;  Ndim = 256; }
    else             { W = Wo; WT = WoT;                          Ndim = 1024; }
    const int n0 = blockIdx.x * 32;
    if (n0 >= Ndim) return;
    const int k0 = blockIdx.y * 32;

    __shared__ float t[32][33];
    const int tx = threadIdx.x, ty = threadIdx.y;
#pragma unroll
    for (int i = 0; i < 32; i += 8)
        t[ty + i][tx] = W[(size_t)(k0 + ty + i) * Ndim + n0 + tx];
    __syncthreads();
#pragma unroll
    for (int i = 0; i < 32; i += 8)
        WT[(size_t)(n0 + ty + i) * 1024 + k0 + tx] = to_tf32(t[tx][ty + i]);
}

// ---------------- tf32 mma.sync GEMM, cp.async double-buffered --------------
#define KP 36
__global__ __launch_bounds__(256) void tgemm(const float* __restrict__ A,
                                             const float* __restrict__ BT,
                                             float* __restrict__ C,
                                             int Ndim, int Kdim)
{
    extern __shared__ float sm[];
    float (*As)[128][KP] = (float (*)[128][KP])sm;
    float (*Bs)[128][KP] = (float (*)[128][KP])(sm + 2 * 128 * KP);

    const int tid = threadIdx.x;
    const int wid = tid >> 5, lane = tid & 31;
    const int g = lane >> 2, tg = lane & 3;
    const int wm = wid & 3, wn = wid >> 2;
    const int rowBase = blockIdx.y << 7;
    const int colBase = blockIdx.x << 7;

    const int cr = tid >> 3, cj = (tid & 7) << 2;
    const uint32_t sA0 = (uint32_t)__cvta_generic_to_shared(&As[0][cr][cj]);
    const uint32_t sA1 = (uint32_t)__cvta_generic_to_shared(&As[1][cr][cj]);
    const uint32_t sB0 = (uint32_t)__cvta_generic_to_shared(&Bs[0][cr][cj]);
    const uint32_t sB1 = (uint32_t)__cvta_generic_to_shared(&Bs[1][cr][cj]);
    const size_t rowStrideB = (size_t)32 * Kdim;
    const float* Agp = A + (size_t)(rowBase + cr) * Kdim + cj;
    const float* Bgp = BT + (size_t)(colBase + cr) * Kdim + cj;

    float c[2][8][4];
#pragma unroll
    for (int mt = 0; mt < 2; mt++)
#pragma unroll
        for (int nt = 0; nt < 8; nt++)
#pragma unroll
            for (int r = 0; r < 4; r++) c[mt][nt][r] = 0.f;

    const int nchunk = Kdim >> 5;
#pragma unroll
    for (int i = 0; i < 4; i++) {
        cp16(sA0 + i * 32 * KP * 4, Agp + i * rowStrideB);
        cp16(sB0 + i * 32 * KP * 4, Bgp + i * rowStrideB);
    }
    CP_COMMIT();

    for (int ch = 0; ch < nchunk; ch++) {
        const int buf = ch & 1;
        if (ch + 1 < nchunk) {
            const uint32_t dA = buf ? sA0 : sA1;
            const uint32_t dB = buf ? sB0 : sB1;
            const float* An = Agp + ((ch + 1) << 5);
            const float* Bn = Bgp + ((ch + 1) << 5);
#pragma unroll
            for (int i = 0; i < 4; i++) {
                cp16(dA + i * 32 * KP * 4, An + i * rowStrideB);
                cp16(dB + i * 32 * KP * 4, Bn + i * rowStrideB);
            }
        }
        CP_COMMIT();
        CP_WAIT1();
        __syncthreads();

        const uint32_t* As32 = (const uint32_t*)&As[buf][0][0];
        const uint32_t* Bs32 = (const uint32_t*)&Bs[buf][0][0];
#pragma unroll
        for (int ks = 0; ks < 4; ks++) {
            const int kk = ks << 3;
            uint32_t a[2][4], b[8][2];
#pragma unroll
            for (int mt = 0; mt < 2; mt++) {
                const int rA = ((wm << 5) + (mt << 4) + g) * KP + kk + tg;
                a[mt][0] = As32[rA];
                a[mt][1] = As32[rA + 8 * KP];
                a[mt][2] = As32[rA + 4];
                a[mt][3] = As32[rA + 8 * KP + 4];
            }
#pragma unroll
            for (int nt = 0; nt < 8; nt++) {
                const int rB = ((wn << 6) + (nt << 3) + g) * KP + kk + tg;
                b[nt][0] = Bs32[rB];
                b[nt][1] = Bs32[rB + 4];
            }
#pragma unroll
            for (int mt = 0; mt < 2; mt++)
#pragma unroll
                for (int nt = 0; nt < 8; nt++)
                    MMA_TF32(c[mt][nt][0], c[mt][nt][1], c[mt][nt][2], c[mt][nt][3],
                             a[mt][0], a[mt][1], a[mt][2], a[mt][3],
                             b[nt][0], b[nt][1]);
        }
        __syncthreads();
    }

#pragma unroll
    for (int mt = 0; mt < 2; mt++) {
        const int row0 = rowBase + (wm << 5) + (mt << 4) + g;
#pragma unroll
        for (int nt = 0; nt < 8; nt++) {
            const int col = colBase + (wn << 6) + (nt << 3) + (tg << 1);
            *(float2*)(C + (size_t)row0 * Ndim + col)       = make_float2(c[mt][nt][0], c[mt][nt][1]);
            *(float2*)(C + (size_t)(row0 + 8) * Ndim + col) = make_float2(c[mt][nt][2], c[mt][nt][3]);
        }
    }
}

// ---------------- L2-normalize + RoPE; outputs tf32-rounded -----------------
__global__ __launch_bounds__(256) void normrope_kernel(const float* __restrict__ cosb,
                                                       const float* __restrict__ sinb)
{
    const int gwarp = (blockIdx.x * blockDim.x + threadIdx.x) >> 5;
    const int lane = threadIdx.x & 31;
    if (gwarp >= M_ * 24) return;
    const int slot = gwarp % 24;
    const int m = gwarp / 24;
    const int b = m / S_, s = m % S_;

    if (slot < 16) {
        const int h = slot;
        const float* src = g_qkv + (size_t)m * 1536 + h * 64;
        float v0 = src[lane], v1 = src[lane + 32];
        float ss = v0 * v0 + v1 * v1;
#pragma unroll
        for (int o = 16; o; o >>= 1) ss += __shfl_xor_sync(0xffffffffu, ss, o);
        float inv = 1.0f / (sqrtf(ss) + 1e-8f);
        float x1 = v0 * inv, x2 = v1 * inv;
        float cc = cosb[s * 32 + lane], sn = sinb[s * 32 + lane];
        float* dst = g_Q + ((size_t)(b * NH_ + h) * S_ + s) * DH_;
        dst[lane]      = to_tf32(x1 * cc - x2 * sn);
        dst[lane + 32] = to_tf32(x1 * sn + x2 * cc);
    } else if (slot < 20) {
        const int h = slot - 16;
        const float* src = g_qkv + (size_t)m * 1536 + 1024 + h * 64;
        float v0 = src[lane], v1 = src[lane + 32];
        float ss = v0 * v0 + v1 * v1;
#pragma unroll
        for (int o = 16; o; o >>= 1) ss += __shfl_xor_sync(0xffffffffu, ss, o);
        float inv = 1.0f / (sqrtf(ss) + 1e-8f);
        float x1 = v0 * inv, x2 = v1 * inv;
        float cc = cosb[s * 32 + lane], sn = sinb[s * 32 + lane];
        float* dst = g_K + ((size_t)(b * NKV_ + h) * S_ + s) * DH_;
        dst[lane]      = to_tf32(x1 * cc - x2 * sn);
        dst[lane + 32] = to_tf32(x1 * sn + x2 * cc);
    } else {
        const int h = slot - 20;
        const float* src = g_qkv + (size_t)m * 1536 + 1280 + h * 64;
        float* dst = g_V + ((size_t)(b * NKV_ + h) * S_ + s) * DH_;
        dst[lane]      = to_tf32(src[lane]);
        dst[lane + 32] = to_tf32(src[lane + 32]);
    }
}

// ---------------- GQA tensor-core attention (512 threads) -------------------
// CTA = 64 queries x 4 heads (one KV group). 512 threads = 16 warps.
// Warp w: head hq = w>>2, query rows (w&3)*16 + [0,16). Q fragments in regs.
// K/V staged once per tile for all 4 heads, cp.async double-buffered.
// K,P stride 68; V stride 72 (natural [key][d], conflict-free B frags).
// qt reversed so heavy CTAs (many key tiles) schedule in wave 1.
#define KS_ 68
#define VS_ 72
__global__ __launch_bounds__(512) void attn_kernel()
{
    extern __shared__ float sm[];
    float* Ksm = sm;                    // [2][64*KS_]
    float* Vsm = sm + 2 * 64 * KS_;     // [2][64*VS_]
    float* Ps  = sm + 2 * 64 * (KS_ + VS_);   // [256][KS_]

    const int qt = (int)gridDim.x - 1 - (int)blockIdx.x;   // reversed: heavy first
    const int hk = blockIdx.y, b = blockIdx.z;
    const int qs = qt << 6;
    const int tid = threadIdx.x;
    const int wid = tid >> 5, lane = tid & 31;
    const int g = lane >> 2, tg = lane & 3;
    const int hq = wid >> 2, q4 = wid & 3;
    const int h = (hk << 2) + hq;

    const float* Qg = g_Q + (size_t)(b * NH_ + h) * S_ * DH_;
    const float* Kg = g_K + (size_t)(b * NKV_ + hk) * S_ * DH_;
    const float* Vg = g_V + (size_t)(b * NKV_ + hk) * S_ * DH_;

    // Q fragments -> registers (16 rows per warp, reused across key tiles)
    const int rloc = (q4 << 4) + g;     // local row (lower 8x8 of the m16 tile)
    uint32_t qa[8][4];
#pragma unroll
    for (int kk = 0; kk < 8; kk++) {
        const float* qp = Qg + (size_t)(qs + rloc) * DH_ + (kk << 3) + tg;
        qa[kk][0] = __float_as_uint(qp[0]);
        qa[kk][1] = __float_as_uint(qp[8 * DH_]);
        qa[kk][2] = __float_as_uint(qp[4]);
        qa[kk][3] = __float_as_uint(qp[8 * DH_ + 4]);
    }

    float o[8][4];
#pragma unroll
    for (int nt = 0; nt < 8; nt++)
#pragma unroll
        for (int r = 0; r < 4; r++) o[nt][r] = 0.f;
    float lacc[2] = {0.f, 0.f};

    const int t_lo = (qs > 255) ? ((qs - 255) >> 6) : 0;
    const int extra = (t_lo > 0) ? 1 : 0;
    const int ntiles = (qt - t_lo + 1) + extra;

    // staging mapping: 8 threads/row, 8 floats per thread (2 cp16) per matrix
    const int sr = tid >> 3, sc = (tid & 7) << 3;
    const uint32_t kb0 = (uint32_t)__cvta_generic_to_shared(Ksm) + (sr * KS_ + sc) * 4;
    const uint32_t vb0 = (uint32_t)__cvta_generic_to_shared(Vsm) + (sr * VS_ + sc) * 4;
    const uint32_t kbufStride = 64 * KS_ * 4, vbufStride = 64 * VS_ * 4;

    // prologue: stage tile 0 into buf 0
    {
        const int ks0 = (extra ? 0 : t_lo) << 6;
        const float* kp = Kg + (size_t)(ks0 + sr) * DH_ + sc;
        const float* vp = Vg + (size_t)(ks0 + sr) * DH_ + sc;
        cp16(kb0,      kp);
        cp16(kb0 + 16, kp + 4);
        cp16(vb0,      vp);
        cp16(vb0 + 16, vp + 4);
    }
    CP_COMMIT();

    const int prow0 = (wid << 4) + g;   // this warp's P slab row

    for (int it = 0; it < ntiles; it++) {
        const int buf = it & 1;
        const int kt = (extra && it == 0) ? 0 : (t_lo + it - extra);
        const int ks = kt << 6;

        if (it + 1 < ntiles) {
            const int ksn = ((extra && it == 0) ? t_lo : (kt + 1)) << 6;
            const uint32_t dk = kb0 + (buf ^ 1) * kbufStride;
            const uint32_t dv = vb0 + (buf ^ 1) * vbufStride;
            const float* kp = Kg + (size_t)(ksn + sr) * DH_ + sc;
            const float* vp = Vg + (size_t)(ksn + sr) * DH_ + sc;
            cp16(dk,      kp);
            cp16(dk + 16, kp + 4);
            cp16(dv,      vp);
            cp16(dv + 16, vp + 4);
        }
        CP_COMMIT();
        CP_WAIT1();
        __syncthreads();

        // S = Q K^T
        float c[8][4];
#pragma unroll
        for (int nt = 0; nt < 8; nt++)
#pragma unroll
            for (int r = 0; r < 4; r++) c[nt][r] = 0.f;

        const uint32_t* K32 = (const uint32_t*)(Ksm + buf * 64 * KS_);
#pragma unroll
        for (int kk = 0; kk < 8; kk++) {
            const int kb = kk << 3;
#pragma unroll
            for (int nt = 0; nt < 8; nt++) {
                const int rB = ((nt << 3) + g) * KS_ + kb + tg;
                const uint32_t b0 = K32[rB];
                const uint32_t b1 = K32[rB + 4];
                MMA_TF32(c[nt][0], c[nt][1], c[nt][2], c[nt][3],
                         qa[kk][0], qa[kk][1], qa[kk][2], qa[kk][3], b0, b1);
            }
        }

        // softcap + exp (poly) + mask -> P, l
        const int rowL = qs + rloc;
#pragma unroll
        for (int nt = 0; nt < 8; nt++) {
            float p[4];
#pragma unroll
            for (int i = 0; i < 4; i++) {
                const int key = ks + (nt << 3) + (tg << 1) + (i & 1);
                const int row = rowL + ((i >> 1) << 3);
                const bool valid = (key <= row) && ((key > row - 256) || (key < 4));
                float t = c[nt][i] * 0.125f;
                float u = t - t * t * t * 1.4814815e-3f;
                float e = fmaf(u, 0.041666668f, 0.16666667f);
                e = fmaf(u, e, 0.5f);
                e = fmaf(u, e, 1.0f);
                e = fmaf(u, e, 1.0f);
                p[i] = valid ? to_tf32(e) : 0.f;
            }
            lacc[0] += p[0] + p[1];
            lacc[1] += p[2] + p[3];
            *(float2*)&Ps[prow0 * KS_ + (nt << 3) + (tg << 1)]       = make_float2(p[0], p[1]);
            *(float2*)&Ps[(prow0 + 8) * KS_ + (nt << 3) + (tg << 1)] = make_float2(p[2], p[3]);
        }
        __syncwarp();

        // O += P V
        const uint32_t* P32 = (const uint32_t*)Ps;
        const uint32_t* V32 = (const uint32_t*)(Vsm + buf * 64 * VS_);
#pragma unroll
        for (int kk = 0; kk < 8; kk++) {
            const int kb = kk << 3;
            const int rP = prow0 * KS_ + kb + tg;
            const uint32_t a0 = P32[rP];
            const uint32_t a1 = P32[rP + 8 * KS_];
            const uint32_t a2 = P32[rP + 4];
            const uint32_t a3 = P32[rP + 8 * KS_ + 4];
#pragma unroll
            for (int nt = 0; nt < 8; nt++) {
                const uint32_t b0 = V32[(kb + tg) * VS_ + (nt << 3) + g];
                const uint32_t b1 = V32[(kb + tg + 4) * VS_ + (nt << 3) + g];
                MMA_TF32(o[nt][0], o[nt][1], o[nt][2], o[nt][3], a0, a1, a2, a3, b0, b1);
            }
        }
        __syncthreads();   // all warps done with buf before it is re-staged
    }

    // reduce l over quad, normalize, write ctx (tf32-rounded)
#pragma unroll
    for (int u = 0; u < 2; u++) {
        lacc[u] += __shfl_xor_sync(0xffffffffu, lacc[u], 1);
        lacc[u] += __shfl_xor_sync(0xffffffffu, lacc[u], 2);
    }
    const float inv0 = 1.0f / lacc[0];
    const float inv1 = 1.0f / lacc[1];

    float* c0 = g_ctx + (size_t)(b * S_ + qs + rloc) * 1024 + h * 64;
    float* c1 = c0 + (size_t)8 * 1024;
#pragma unroll
    for (int nt = 0; nt < 8; nt++) {
        const int d = (nt << 3) + (tg << 1);
        *(float2*)(c0 + d) = make_float2(to_tf32(o[nt][0] * inv0),
                                         to_tf32(o[nt][1] * inv0));
        *(float2*)(c1 + d) = make_float2(to_tf32(o[nt][2] * inv1),
                                         to_tf32(o[nt][3] * inv1));
    }
}

// ---------------- launch -----------------------------------------------------
extern "C" void kernel_launch(void* const* d_in, const int* in_sizes, int n_in,
                              void* d_out, int out_size)
{
    const float* x    = (const float*)d_in[0];
    const float* cosb = (const float*)d_in[1];
    const float* sinb = (const float*)d_in[2];
    const float* Wq   = (const float*)d_in[4];
    const float* Wk   = (const float*)d_in[5];
    const float* Wv   = (const float*)d_in[6];
    const float* Wo   = (const float*)d_in[7];
    float* out = (float*)d_out;

    float *xr, *qkv, *ctx, *wqkvT, *woT;
    cudaGetSymbolAddress((void**)&xr,    g_xr);
    cudaGetSymbolAddress((void**)&qkv,   g_qkv);
    cudaGetSymbolAddress((void**)&ctx,   g_ctx);
    cudaGetSymbolAddress((void**)&wqkvT, g_WqkvT);
    cudaGetSymbolAddress((void**)&woT,   g_WoT);

    xround<<<(M_ * 1024) / (256 * 4), 256>>>(x, xr);
    wtrans4<<<dim3(32, 32, 4), dim3(32, 8)>>>(Wq, Wk, Wv, Wo, wqkvT, woT);

    const int gsmem = 4 * 128 * KP * (int)sizeof(float);
    cudaFuncSetAttribute(tgemm, cudaFuncAttributeMaxDynamicSharedMemorySize, gsmem);

    tgemm<<<dim3(12, 32), 256, gsmem>>>(xr, wqkvT, qkv, 1536, 1024);

    normrope_kernel<<<(M_ * 24) / 8, 256>>>(cosb, sinb);

    const int asmem = (2 * 64 * (KS_ + VS_) + 256 * KS_) * (int)sizeof(float);
    cudaFuncSetAttribute(attn_kernel, cudaFuncAttributeMaxDynamicSharedMemorySize, asmem);
    attn_kernel<<<dim3(S_ / 64, NKV_, B_), 512, asmem>>>();

    tgemm<<<dim3(8, 32), 256, gsmem>>>(ctx, woT, out, 1024, 1024);
}